// round 15
// baseline (speedup 1.0000x reference)
#include <cuda_runtime.h>
#include <cuda_fp16.h>
#include <math.h>
#include <stdint.h>

#define N_NODES 100000
#define E_EDGES 1600000
#define C_DIM 256
#define H_DIM 128
#define F_DIM 64

// Scratch (__device__ globals; no allocation allowed)
__device__ __half g_hbuf1[N_NODES * H_DIM];   // GEMM outputs (pre-aggregation)
__device__ __half g_hbuf2[N_NODES * H_DIM];   // SpMM outputs (activations)
__device__ __half g_Wh[57344];                // fp16 W0 | Wh0 | W1
__device__ int    g_rowptr[N_NODES + 1];

// ---------------------------------------------------------------------------
// Helpers
// ---------------------------------------------------------------------------
__device__ __forceinline__ uint32_t smem_u32(const void* p) {
    uint32_t a;
    asm("{ .reg .u64 t; cvta.to.shared.u64 t, %1; cvt.u32.u64 %0, t; }" : "=r"(a) : "l"(p));
    return a;
}
__device__ __forceinline__ void ldsm_x4(uint32_t (&r)[4], uint32_t addr) {
    asm volatile("ldmatrix.sync.aligned.m8n8.x4.shared.b16 {%0,%1,%2,%3}, [%4];"
                 : "=r"(r[0]), "=r"(r[1]), "=r"(r[2]), "=r"(r[3]) : "r"(addr));
}
__device__ __forceinline__ void mma_f16(float (&d)[4], const uint32_t (&a)[4],
                                        uint32_t b0, uint32_t b1) {
    asm volatile(
        "mma.sync.aligned.m16n8k16.row.col.f32.f16.f16.f32 "
        "{%0,%1,%2,%3}, {%4,%5,%6,%7}, {%8,%9}, {%0,%1,%2,%3};"
        : "+f"(d[0]), "+f"(d[1]), "+f"(d[2]), "+f"(d[3])
        : "r"(a[0]), "r"(a[1]), "r"(a[2]), "r"(a[3]), "r"(b0), "r"(b1));
}
__device__ __forceinline__ void cp_async16(uint32_t dst, const void* src, int srcsize) {
    asm volatile("cp.async.cg.shared.global [%0], [%1], 16, %2;"
                 :: "r"(dst), "l"(src), "r"(srcsize));
}
#define CP_COMMIT() asm volatile("cp.async.commit_group;" ::: "memory")
template<int NW> __device__ __forceinline__ void cp_wait() {
    asm volatile("cp.async.wait_group %0;" :: "n"(NW) : "memory");
}
__device__ __forceinline__ uint32_t pack_h2(float2 v) {
    __half2 h = __floats2half2_rn(v.x, v.y);
    return *reinterpret_cast<uint32_t*>(&h);
}

// Packed f32x2 (Blackwell FFMA2) — bit-identical to scalar fmaf pairs.
__device__ __forceinline__ uint64_t pack_f32x2(float lo, float hi) {
    uint64_t r;
    asm("mov.b64 %0, {%1, %2};" : "=l"(r) : "f"(lo), "f"(hi));
    return r;
}
__device__ __forceinline__ void unpack_f32x2(uint64_t v, float& lo, float& hi) {
    asm("mov.b64 {%0, %1}, %2;" : "=f"(lo), "=f"(hi) : "l"(v));
}
__device__ __forceinline__ void ffma2(uint64_t& d, uint64_t a, uint64_t b) {
    asm("fma.rn.f32x2 %0, %1, %2, %0;" : "+l"(d) : "l"(a), "l"(b));
}

// ---------------------------------------------------------------------------
// Prep: rowptr + merged weight cast in ONE launch
// ---------------------------------------------------------------------------
__global__ void prep_kernel(const int* __restrict__ edge_row,
                            const float* __restrict__ W0,
                            const float* __restrict__ Wh0,
                            const float* __restrict__ W1,
                            __half* __restrict__ dst) {
    int i = blockIdx.x * blockDim.x + threadIdx.x;
    if (i <= N_NODES) {
        int lo = 0, hi = E_EDGES;
        while (lo < hi) {
            int mid = (lo + hi) >> 1;
            if (edge_row[mid] < i) lo = mid + 1;
            else hi = mid;
        }
        g_rowptr[i] = lo;
    }
    if (i < 14336) {                              // 57344 / 4 float4 groups
        const float* src;
        int j;
        if (i < 8192)       { src = W0;  j = i; }
        else if (i < 12288) { src = Wh0; j = i - 8192; }
        else                { src = W1;  j = i - 12288; }
        float4 v = reinterpret_cast<const float4*>(src)[j];
        uint2 o = make_uint2(pack_h2(make_float2(v.x, v.y)),
                             pack_h2(make_float2(v.z, v.w)));
        reinterpret_cast<uint2*>(dst)[i] = o;
    }
}

// ---------------------------------------------------------------------------
// Layer-0 GEMM: A fp32 (staged raw, cvt on fragment load), W fp16 (ldmatrix).
// BM=64 tile, 3 stages, 3 CTAs/SM.
// ---------------------------------------------------------------------------
__global__ void __launch_bounds__(256, 3) gemm_l0(const float* __restrict__ A,
                                                  const __half* __restrict__ W,
                                                  __half* __restrict__ out, int M) {
    constexpr int BM = 64, N = 128, K = 256, BK = 32;
    constexpr int NC = K / BK;                  // 8
    constexpr int LDSA = 40;                    // floats per A row (160B)
    constexpr int ABYTES = BM * LDSA * 4;       // 10240
    constexpr int LDSW = 80;                    // bytes per W row
    constexpr int WBYTES = N * LDSW;            // 10240
    constexpr int STAGEB = ABYTES + WBYTES;     // 20480 (x3 = 61440)
    constexpr int MT = 2;

    extern __shared__ char smem[];
    const uint32_t sb = smem_u32(smem);

    const int tid  = threadIdx.x;
    const int wid  = tid >> 5;
    const int lane = tid & 31;
    const int wm   = (wid >> 2) * 32;
    const int wn   = (wid & 3) * 32;
    const int bm   = blockIdx.x * BM;
    const int arows = min(BM, M - bm);

    const int fr    = lane >> 2;
    const int fc    = lane & 3;
    const int lrow  = lane & 15;
    const int lcolb = (lane >> 4) * 16;

    float acc[MT][4][4];
#pragma unroll
    for (int i = 0; i < MT; i++)
#pragma unroll
        for (int j = 0; j < 4; j++)
#pragma unroll
            for (int c = 0; c < 4; c++) acc[i][j][c] = 0.f;

    auto fill = [&](int s, int k0) {
        const uint32_t base = sb + (uint32_t)(s * STAGEB);
#pragma unroll
        for (int idx = tid; idx < BM * 8; idx += 256) {
            int row = idx >> 3, g = idx & 7;
            int sz = (row < arows) ? 16 : 0;
            cp_async16(base + (uint32_t)(row * 160 + g * 16),
                       &A[(size_t)(bm + row) * K + k0 + g * 4], sz);
        }
#pragma unroll
        for (int idx = tid; idx < N * 4; idx += 256) {
            int row = idx >> 2, g = idx & 3;
            cp_async16(base + (uint32_t)(ABYTES + row * LDSW + g * 16),
                       &W[(size_t)row * K + k0 + g * 8], 16);
        }
        CP_COMMIT();
    };

    fill(0, 0);
    fill(1, BK);

    for (int kc = 0; kc < NC; kc++) {
        if (kc + 1 < NC) cp_wait<1>(); else cp_wait<0>();
        __syncthreads();

        const char*  stg = smem + (kc % 3) * STAGEB;
        const float* sA  = reinterpret_cast<const float*>(stg);
        const uint32_t wB = sb + (uint32_t)((kc % 3) * STAGEB + ABYTES);

#pragma unroll
        for (int ks = 0; ks < 2; ks++) {
            uint32_t af[MT][4];
#pragma unroll
            for (int mt = 0; mt < MT; mt++) {
                int base = (wm + mt * 16 + fr) * LDSA + ks * 16 + fc * 2;
                float2 v0 = *reinterpret_cast<const float2*>(&sA[base]);
                float2 v1 = *reinterpret_cast<const float2*>(&sA[base + 8 * LDSA]);
                float2 v2 = *reinterpret_cast<const float2*>(&sA[base + 8]);
                float2 v3 = *reinterpret_cast<const float2*>(&sA[base + 8 * LDSA + 8]);
                af[mt][0] = pack_h2(v0);
                af[mt][1] = pack_h2(v1);
                af[mt][2] = pack_h2(v2);
                af[mt][3] = pack_h2(v3);
            }
            uint32_t bf[2][4];
#pragma unroll
            for (int np = 0; np < 2; np++)
                ldsm_x4(bf[np], wB + (uint32_t)((wn + np * 16 + lrow) * LDSW
                                                + ks * 32 + lcolb));
#pragma unroll
            for (int mt = 0; mt < MT; mt++)
#pragma unroll
                for (int nt = 0; nt < 4; nt++) {
                    int np = nt >> 1, h = nt & 1;
                    mma_f16(acc[mt][nt], af[mt], bf[np][h], bf[np][h + 2]);
                }
        }

        if (kc + 2 < NC) fill((kc + 2) % 3, (kc + 2) * BK);
    }

#pragma unroll
    for (int mt = 0; mt < MT; mt++) {
#pragma unroll
        for (int nt = 0; nt < 4; nt++) {
            int r0 = wm + mt * 16 + fr;
            int c0 = wn + nt * 8 + fc * 2;
            if (r0 < arows)
                *reinterpret_cast<__half2*>(&out[(size_t)(bm + r0) * N + c0]) =
                    __floats2half2_rn(acc[mt][nt][0], acc[mt][nt][1]);
            if (r0 + 8 < arows)
                *reinterpret_cast<__half2*>(&out[(size_t)(bm + r0 + 8) * N + c0]) =
                    __floats2half2_rn(acc[mt][nt][2], acc[mt][nt][3]);
        }
    }
}

// ---------------------------------------------------------------------------
// fp16 HMMA GEMM (layers 1-2): BM=64, BK=32, 3-stage cp.async, 3 CTAs/SM.
// Warp grid: N=128 -> 2x4 (warp 32x32, MT=2); N=64 -> 4x2 (warp 16x32, MT=1).
// Smem rows: 32 halves + 8 pad = 80B stride (ldmatrix conflict-free, proven
// by the gemm_l0 W-tile pattern). K-step order unchanged -> bit-identical.
// ---------------------------------------------------------------------------
template<int N, int K>
__global__ void __launch_bounds__(256, 3) gemm_h(const __half* __restrict__ A,
                                                 const __half* __restrict__ W,
                                                 __half* __restrict__ out, int M) {
    constexpr int BM = 64;
    constexpr int BK = 32;
    constexpr int LDS = 80;                    // bytes per smem row
    constexpr int ABYTES = BM * LDS;           // 5120
    constexpr int WBYTES = N * LDS;
    constexpr int STAGEB = ABYTES + WBYTES;
    constexpr int NC = K / BK;                 // 4
    constexpr int WCOLS = N / 32;              // 4 or 2
    constexpr int WROWS = 8 / WCOLS;           // 2 or 4
    constexpr int WTM = BM / WROWS;            // 32 or 16
    constexpr int MT = WTM / 16;               // 2 or 1

    extern __shared__ char smem[];
    const uint32_t sb = smem_u32(smem);

    const int tid  = threadIdx.x;
    const int wid  = tid >> 5;
    const int lane = tid & 31;
    const int wm   = (wid / WCOLS) * WTM;
    const int wn   = (wid % WCOLS) * 32;
    const int bm   = blockIdx.x * BM;
    const int arows = min(BM, M - bm);

    const int lrow  = lane & 15;
    const int lcolb = (lane >> 4) * 16;

    float acc[MT][4][4];
#pragma unroll
    for (int i = 0; i < MT; i++)
#pragma unroll
        for (int j = 0; j < 4; j++)
#pragma unroll
            for (int c = 0; c < 4; c++) acc[i][j][c] = 0.f;

    auto fill = [&](int s, int k0) {
        const uint32_t base = sb + (uint32_t)(s * STAGEB);
#pragma unroll
        for (int idx = tid; idx < BM * 4; idx += 256) {      // 1 iter
            int row = idx >> 2, g = idx & 3;
            int sz = (row < arows) ? 16 : 0;
            cp_async16(base + (uint32_t)(row * LDS + g * 16),
                       &A[(size_t)(bm + row) * K + k0 + g * 8], sz);
        }
#pragma unroll
        for (int idx = tid; idx < N * 4; idx += 256) {       // 2 or 1 iters
            int row = idx >> 2, g = idx & 3;
            cp_async16(base + (uint32_t)(ABYTES + row * LDS + g * 16),
                       &W[(size_t)row * K + k0 + g * 8], 16);
        }
        CP_COMMIT();
    };

    fill(0, 0);
    fill(1, BK);

    for (int kc = 0; kc < NC; kc++) {
        if (kc + 1 < NC) cp_wait<1>(); else cp_wait<0>();
        __syncthreads();

        const uint32_t st = sb + (uint32_t)((kc % 3) * STAGEB);
        const uint32_t aB = st;
        const uint32_t wB = st + ABYTES;

#pragma unroll
        for (int ks = 0; ks < 2; ks++) {                     // 2 k16 steps
            const uint32_t cb = (uint32_t)(ks * 32 + lcolb);
            uint32_t af[MT][4];
#pragma unroll
            for (int mt = 0; mt < MT; mt++)
                ldsm_x4(af[mt], aB + (uint32_t)((wm + mt * 16 + lrow) * LDS) + cb);
            uint32_t bf[2][4];
#pragma unroll
            for (int np = 0; np < 2; np++)
                ldsm_x4(bf[np], wB + (uint32_t)((wn + np * 16 + lrow) * LDS) + cb);
#pragma unroll
            for (int mt = 0; mt < MT; mt++)
#pragma unroll
                for (int nt = 0; nt < 4; nt++) {
                    int np = nt >> 1, h = nt & 1;
                    mma_f16(acc[mt][nt], af[mt], bf[np][h], bf[np][h + 2]);
                }
        }

        if (kc + 2 < NC) fill((kc + 2) % 3, (kc + 2) * BK);
    }

#pragma unroll
    for (int mt = 0; mt < MT; mt++) {
#pragma unroll
        for (int nt = 0; nt < 4; nt++) {
            int r0 = wm + mt * 16 + (lane >> 2);
            int c0 = wn + nt * 8 + (lane & 3) * 2;
            if (r0 < arows)
                *reinterpret_cast<__half2*>(&out[(size_t)(bm + r0) * N + c0]) =
                    __floats2half2_rn(acc[mt][nt][0], acc[mt][nt][1]);
            if (r0 + 8 < arows)
                *reinterpret_cast<__half2*>(&out[(size_t)(bm + r0 + 8) * N + c0]) =
                    __floats2half2_rn(acc[mt][nt][2], acc[mt][nt][3]);
        }
    }
}

// ---------------------------------------------------------------------------
// SpMM (H=128), fp16 gather / packed-f32x2 accumulate / ReLU / fp16 store.
// ---------------------------------------------------------------------------
__device__ __forceinline__ void fma_h4p(uint64_t& a01, uint64_t& a23,
                                        uint64_t vv, uint2 zz) {
    float2 f0 = __half22float2(*reinterpret_cast<__half2*>(&zz.x));
    float2 f1 = __half22float2(*reinterpret_cast<__half2*>(&zz.y));
    ffma2(a01, vv, pack_f32x2(f0.x, f0.y));
    ffma2(a23, vv, pack_f32x2(f1.x, f1.y));
}

__global__ void __launch_bounds__(256) spmm128_h_kernel(const int* __restrict__ edge_col,
                                                        const float* __restrict__ edge_val,
                                                        const __half* __restrict__ Z,
                                                        __half* __restrict__ out) {
    int gw   = (blockIdx.x * blockDim.x + threadIdx.x) >> 5;
    int lane = threadIdx.x & 31;
    if (gw >= N_NODES) return;
    int s = g_rowptr[gw];
    int e = g_rowptr[gw + 1];

    uint64_t a01 = pack_f32x2(0.f, 0.f);
    uint64_t a23 = pack_f32x2(0.f, 0.f);
    int i = s;
    for (; i + 8 <= e; i += 8) {
        int   c[8];
        float v[8];
        uint2 z[8];
#pragma unroll
        for (int u = 0; u < 8; u++) {
            c[u] = __ldg(&edge_col[i + u]);
            v[u] = __ldg(&edge_val[i + u]);
        }
#pragma unroll
        for (int u = 0; u < 8; u++)
            z[u] = *reinterpret_cast<const uint2*>(&Z[(size_t)c[u] * H_DIM + lane * 4]);
#pragma unroll
        for (int u = 0; u < 8; u++)
            fma_h4p(a01, a23, pack_f32x2(v[u], v[u]), z[u]);
    }
    for (; i < e; i++) {
        int   col = __ldg(&edge_col[i]);
        float val = __ldg(&edge_val[i]);
        uint2 zz = *reinterpret_cast<const uint2*>(&Z[(size_t)col * H_DIM + lane * 4]);
        fma_h4p(a01, a23, pack_f32x2(val, val), zz);
    }
    float4 acc;
    unpack_f32x2(a01, acc.x, acc.y);
    unpack_f32x2(a23, acc.z, acc.w);
    acc.x = fmaxf(acc.x, 0.f);
    acc.y = fmaxf(acc.y, 0.f);
    acc.z = fmaxf(acc.z, 0.f);
    acc.w = fmaxf(acc.w, 0.f);
    uint2 ov = make_uint2(pack_h2(make_float2(acc.x, acc.y)),
                          pack_h2(make_float2(acc.z, acc.w)));
    *reinterpret_cast<uint2*>(&out[(size_t)gw * H_DIM + lane * 4]) = ov;
}

// ---------------------------------------------------------------------------
// Final SpMM (F=64), fp16 gather, packed-f32x2 accumulate, fused row softmax.
// ---------------------------------------------------------------------------
__global__ void __launch_bounds__(256) spmm64_softmax_kernel(const int* __restrict__ edge_col,
                                                             const float* __restrict__ edge_val,
                                                             const __half* __restrict__ Z,
                                                             float* __restrict__ out) {
    int gw   = (blockIdx.x * blockDim.x + threadIdx.x) >> 5;
    int lane = threadIdx.x & 31;
    if (gw >= N_NODES) return;
    int s = g_rowptr[gw];
    int e = g_rowptr[gw + 1];

    uint64_t a01 = pack_f32x2(0.f, 0.f);
    int i = s;
    for (; i + 4 <= e; i += 4) {
#pragma unroll
        for (int u = 0; u < 4; u++) {
            int   col = __ldg(&edge_col[i + u]);
            float val = __ldg(&edge_val[i + u]);
            uint32_t zz = *reinterpret_cast<const uint32_t*>(&Z[(size_t)col * F_DIM + lane * 2]);
            float2 f = __half22float2(*reinterpret_cast<__half2*>(&zz));
            ffma2(a01, pack_f32x2(val, val), pack_f32x2(f.x, f.y));
        }
    }
    for (; i < e; i++) {
        int   col = __ldg(&edge_col[i]);
        float val = __ldg(&edge_val[i]);
        uint32_t zz = *reinterpret_cast<const uint32_t*>(&Z[(size_t)col * F_DIM + lane * 2]);
        float2 f = __half22float2(*reinterpret_cast<__half2*>(&zz));
        ffma2(a01, pack_f32x2(val, val), pack_f32x2(f.x, f.y));
    }
    float a0, a1;
    unpack_f32x2(a01, a0, a1);
    float m = fmaxf(a0, a1);
#pragma unroll
    for (int off = 16; off > 0; off >>= 1)
        m = fmaxf(m, __shfl_xor_sync(0xFFFFFFFFu, m, off));
    float e0 = expf(a0 - m);
    float e1 = expf(a1 - m);
    float ssum = e0 + e1;
#pragma unroll
    for (int off = 16; off > 0; off >>= 1)
        ssum += __shfl_xor_sync(0xFFFFFFFFu, ssum, off);
    float inv = 1.0f / ssum;
    *reinterpret_cast<float2*>(&out[(size_t)gw * F_DIM + lane * 2]) =
        make_float2(e0 * inv, e1 * inv);
}

// ---------------------------------------------------------------------------
// Launch
// ---------------------------------------------------------------------------
extern "C" void kernel_launch(void* const* d_in, const int* in_sizes, int n_in,
                              void* d_out, int out_size) {
    const float* X        = (const float*)d_in[0];
    const int*   edge_row = (const int*)d_in[1];
    const int*   edge_col = (const int*)d_in[2];
    const float* edge_val = (const float*)d_in[3];
    const float* W0       = (const float*)d_in[4];
    const float* Wh0      = (const float*)d_in[5];
    const float* W1       = (const float*)d_in[6];
    float*       out      = (float*)d_out;

    __half *h1, *h2, *Wh;
    cudaGetSymbolAddress((void**)&h1, g_hbuf1);
    cudaGetSymbolAddress((void**)&h2, g_hbuf2);
    cudaGetSymbolAddress((void**)&Wh, g_Wh);

    constexpr int SMEM_L0   = 3 * (64 * 160 + 128 * 80);   // 61440
    constexpr int SMEM_H128 = 3 * (64 * 80 + 128 * 80);    // 46080
    constexpr int SMEM_H64  = 3 * (64 * 80 + 64 * 80);     // 30720
    cudaFuncSetAttribute((const void*)gemm_l0,
                         cudaFuncAttributeMaxDynamicSharedMemorySize, SMEM_L0);
    cudaFuncSetAttribute((const void*)gemm_h<128, 128>,
                         cudaFuncAttributeMaxDynamicSharedMemorySize, SMEM_H128);
    cudaFuncSetAttribute((const void*)gemm_h<64, 128>,
                         cudaFuncAttributeMaxDynamicSharedMemorySize, SMEM_H64);

    const int g64_grid  = (N_NODES + 63) / 64;         // 1563
    const int spmm_grid = (N_NODES * 32 + 255) / 256;  // 12500

    prep_kernel<<<(N_NODES + 1 + 255) / 256, 256>>>(edge_row, W0, Wh0, W1, Wh);

    // Layer 0: h1 = X @ W0h^T (fused fp32->fp16) ; h2 = relu(A @ h1)
    gemm_l0<<<g64_grid, 256, SMEM_L0>>>(X, Wh, h1, N_NODES);
    spmm128_h_kernel<<<spmm_grid, 256>>>(edge_col, edge_val, h1, h2);

    // Hidden: h1 = h2 @ Wh0h^T ; h2 = relu(A @ h1)
    gemm_h<128, 128><<<g64_grid, 256, SMEM_H128>>>(h2, Wh + 32768, h1, N_NODES);
    spmm128_h_kernel<<<spmm_grid, 256>>>(edge_col, edge_val, h1, h2);

    // Output: h1 = h2 @ W1h^T ; out = softmax(A @ h1)
    gemm_h<64, 128><<<g64_grid, 256, SMEM_H64>>>(h2, Wh + 49152, h1, N_NODES);
    spmm64_softmax_kernel<<<spmm_grid, 256>>>(edge_col, edge_val, h1, out);
}

// round 16
// speedup vs baseline: 1.1020x; 1.1020x over previous
#include <cuda_runtime.h>
#include <cuda_fp16.h>
#include <math.h>
#include <stdint.h>

#define N_NODES 100000
#define E_EDGES 1600000
#define C_DIM 256
#define H_DIM 128
#define F_DIM 64

// Scratch (__device__ globals; no allocation allowed)
__device__ __half g_hbuf1[N_NODES * H_DIM];   // GEMM outputs (pre-aggregation)
__device__ __half g_hbuf2[N_NODES * H_DIM];   // SpMM outputs (activations)
__device__ __half g_Wh[57344];                // fp16 W0 | Wh0 | W1
__device__ int    g_rowptr[N_NODES + 1];

// ---------------------------------------------------------------------------
// Helpers
// ---------------------------------------------------------------------------
__device__ __forceinline__ uint32_t smem_u32(const void* p) {
    uint32_t a;
    asm("{ .reg .u64 t; cvta.to.shared.u64 t, %1; cvt.u32.u64 %0, t; }" : "=r"(a) : "l"(p));
    return a;
}
__device__ __forceinline__ void ldsm_x4(uint32_t (&r)[4], uint32_t addr) {
    asm volatile("ldmatrix.sync.aligned.m8n8.x4.shared.b16 {%0,%1,%2,%3}, [%4];"
                 : "=r"(r[0]), "=r"(r[1]), "=r"(r[2]), "=r"(r[3]) : "r"(addr));
}
__device__ __forceinline__ void mma_f16(float (&d)[4], const uint32_t (&a)[4],
                                        uint32_t b0, uint32_t b1) {
    asm volatile(
        "mma.sync.aligned.m16n8k16.row.col.f32.f16.f16.f32 "
        "{%0,%1,%2,%3}, {%4,%5,%6,%7}, {%8,%9}, {%0,%1,%2,%3};"
        : "+f"(d[0]), "+f"(d[1]), "+f"(d[2]), "+f"(d[3])
        : "r"(a[0]), "r"(a[1]), "r"(a[2]), "r"(a[3]), "r"(b0), "r"(b1));
}
__device__ __forceinline__ void cp_async16(uint32_t dst, const void* src, int srcsize) {
    asm volatile("cp.async.cg.shared.global [%0], [%1], 16, %2;"
                 :: "r"(dst), "l"(src), "r"(srcsize));
}
#define CP_COMMIT() asm volatile("cp.async.commit_group;" ::: "memory")
template<int NW> __device__ __forceinline__ void cp_wait() {
    asm volatile("cp.async.wait_group %0;" :: "n"(NW) : "memory");
}
__device__ __forceinline__ uint32_t pack_h2(float2 v) {
    __half2 h = __floats2half2_rn(v.x, v.y);
    return *reinterpret_cast<uint32_t*>(&h);
}

// Packed f32x2 (Blackwell FFMA2) — bit-identical to scalar fmaf pairs.
__device__ __forceinline__ uint64_t pack_f32x2(float lo, float hi) {
    uint64_t r;
    asm("mov.b64 %0, {%1, %2};" : "=l"(r) : "f"(lo), "f"(hi));
    return r;
}
__device__ __forceinline__ void unpack_f32x2(uint64_t v, float& lo, float& hi) {
    asm("mov.b64 {%0, %1}, %2;" : "=f"(lo), "=f"(hi) : "l"(v));
}
__device__ __forceinline__ void ffma2(uint64_t& d, uint64_t a, uint64_t b) {
    asm("fma.rn.f32x2 %0, %1, %2, %0;" : "+l"(d) : "l"(a), "l"(b));
}

// ---------------------------------------------------------------------------
// Prep: rowptr + merged weight cast in ONE launch
// ---------------------------------------------------------------------------
__global__ void prep_kernel(const int* __restrict__ edge_row,
                            const float* __restrict__ W0,
                            const float* __restrict__ Wh0,
                            const float* __restrict__ W1,
                            __half* __restrict__ dst) {
    int i = blockIdx.x * blockDim.x + threadIdx.x;
    if (i <= N_NODES) {
        int lo = 0, hi = E_EDGES;
        while (lo < hi) {
            int mid = (lo + hi) >> 1;
            if (edge_row[mid] < i) lo = mid + 1;
            else hi = mid;
        }
        g_rowptr[i] = lo;
    }
    if (i < 14336) {                              // 57344 / 4 float4 groups
        const float* src;
        int j;
        if (i < 8192)       { src = W0;  j = i; }
        else if (i < 12288) { src = Wh0; j = i - 8192; }
        else                { src = W1;  j = i - 12288; }
        float4 v = reinterpret_cast<const float4*>(src)[j];
        uint2 o = make_uint2(pack_h2(make_float2(v.x, v.y)),
                             pack_h2(make_float2(v.z, v.w)));
        reinterpret_cast<uint2*>(dst)[i] = o;
    }
}

// ---------------------------------------------------------------------------
// Layer-0 GEMM: A fp32 (staged raw, cvt on fragment load), W fp16 (ldmatrix).
// BM=64 tile, FOUR stages, wait<2> -> 2-3 fill groups in flight during
// compute (DRAM stream stays busy). 2 CTAs/SM.
// ---------------------------------------------------------------------------
__global__ void __launch_bounds__(256, 2) gemm_l0(const float* __restrict__ A,
                                                  const __half* __restrict__ W,
                                                  __half* __restrict__ out, int M) {
    constexpr int BM = 64, N = 128, K = 256, BK = 32;
    constexpr int NC = K / BK;                  // 8
    constexpr int LDSA = 40;                    // floats per A row (160B)
    constexpr int ABYTES = BM * LDSA * 4;       // 10240
    constexpr int LDSW = 80;                    // bytes per W row
    constexpr int WBYTES = N * LDSW;            // 10240
    constexpr int STAGEB = ABYTES + WBYTES;     // 20480 (x4 = 81920)
    constexpr int MT = 2;

    extern __shared__ char smem[];
    const uint32_t sb = smem_u32(smem);

    const int tid  = threadIdx.x;
    const int wid  = tid >> 5;
    const int lane = tid & 31;
    const int wm   = (wid >> 2) * 32;
    const int wn   = (wid & 3) * 32;
    const int bm   = blockIdx.x * BM;
    const int arows = min(BM, M - bm);

    const int fr    = lane >> 2;
    const int fc    = lane & 3;
    const int lrow  = lane & 15;
    const int lcolb = (lane >> 4) * 16;

    float acc[MT][4][4];
#pragma unroll
    for (int i = 0; i < MT; i++)
#pragma unroll
        for (int j = 0; j < 4; j++)
#pragma unroll
            for (int c = 0; c < 4; c++) acc[i][j][c] = 0.f;

    auto fill = [&](int s, int k0) {
        const uint32_t base = sb + (uint32_t)(s * STAGEB);
#pragma unroll
        for (int idx = tid; idx < BM * 8; idx += 256) {
            int row = idx >> 3, g = idx & 7;
            int sz = (row < arows) ? 16 : 0;
            cp_async16(base + (uint32_t)(row * 160 + g * 16),
                       &A[(size_t)(bm + row) * K + k0 + g * 4], sz);
        }
#pragma unroll
        for (int idx = tid; idx < N * 4; idx += 256) {
            int row = idx >> 2, g = idx & 3;
            cp_async16(base + (uint32_t)(ABYTES + row * LDSW + g * 16),
                       &W[(size_t)row * K + k0 + g * 8], 16);
        }
        CP_COMMIT();
    };

    fill(0, 0);
    fill(1, BK);
    fill(2, 2 * BK);

    for (int kc = 0; kc < NC; kc++) {
        if (kc + 2 < NC)      cp_wait<2>();
        else if (kc + 1 < NC) cp_wait<1>();
        else                  cp_wait<0>();
        __syncthreads();

        const char*  stg = smem + (kc & 3) * STAGEB;
        const float* sA  = reinterpret_cast<const float*>(stg);
        const uint32_t wB = sb + (uint32_t)((kc & 3) * STAGEB + ABYTES);

#pragma unroll
        for (int ks = 0; ks < 2; ks++) {
            uint32_t af[MT][4];
#pragma unroll
            for (int mt = 0; mt < MT; mt++) {
                int base = (wm + mt * 16 + fr) * LDSA + ks * 16 + fc * 2;
                float2 v0 = *reinterpret_cast<const float2*>(&sA[base]);
                float2 v1 = *reinterpret_cast<const float2*>(&sA[base + 8 * LDSA]);
                float2 v2 = *reinterpret_cast<const float2*>(&sA[base + 8]);
                float2 v3 = *reinterpret_cast<const float2*>(&sA[base + 8 * LDSA + 8]);
                af[mt][0] = pack_h2(v0);
                af[mt][1] = pack_h2(v1);
                af[mt][2] = pack_h2(v2);
                af[mt][3] = pack_h2(v3);
            }
            uint32_t bf[2][4];
#pragma unroll
            for (int np = 0; np < 2; np++)
                ldsm_x4(bf[np], wB + (uint32_t)((wn + np * 16 + lrow) * LDSW
                                                + ks * 32 + lcolb));
#pragma unroll
            for (int mt = 0; mt < MT; mt++)
#pragma unroll
                for (int nt = 0; nt < 4; nt++) {
                    int np = nt >> 1, h = nt & 1;
                    mma_f16(acc[mt][nt], af[mt], bf[np][h], bf[np][h + 2]);
                }
        }

        if (kc + 3 < NC) fill((kc + 3) & 3, (kc + 3) * BK);
    }

#pragma unroll
    for (int mt = 0; mt < MT; mt++) {
#pragma unroll
        for (int nt = 0; nt < 4; nt++) {
            int r0 = wm + mt * 16 + fr;
            int c0 = wn + nt * 8 + fc * 2;
            if (r0 < arows)
                *reinterpret_cast<__half2*>(&out[(size_t)(bm + r0) * N + c0]) =
                    __floats2half2_rn(acc[mt][nt][0], acc[mt][nt][1]);
            if (r0 + 8 < arows)
                *reinterpret_cast<__half2*>(&out[(size_t)(bm + r0 + 8) * N + c0]) =
                    __floats2half2_rn(acc[mt][nt][2], acc[mt][nt][3]);
        }
    }
}

// ---------------------------------------------------------------------------
// fp16 HMMA GEMM (layers 1-2): R14-proven config. BM=128, BK=64, 3-stage,
// 2 CTAs/SM. Smem rows: 144B stride.
// ---------------------------------------------------------------------------
template<int N, int K>
__global__ void __launch_bounds__(256, 2) gemm_h(const __half* __restrict__ A,
                                                 const __half* __restrict__ W,
                                                 __half* __restrict__ out, int M) {
    constexpr int BM = 128;
    constexpr int LDS = 144;
    constexpr int ABYTES = BM * LDS;
    constexpr int WBYTES = N * LDS;
    constexpr int STAGEB = ABYTES + WBYTES;
    constexpr int NC = K / 64;
    constexpr int WCOLS = N / 32;
    constexpr int WTM = BM / (8 / WCOLS);
    constexpr int MT = WTM / 16;

    extern __shared__ char smem[];
    const uint32_t sb = smem_u32(smem);

    const int tid  = threadIdx.x;
    const int wid  = tid >> 5;
    const int lane = tid & 31;
    const int wm   = (wid / WCOLS) * WTM;
    const int wn   = (wid % WCOLS) * 32;
    const int bm   = blockIdx.x * BM;
    const int arows = min(BM, M - bm);

    const int lrow  = lane & 15;
    const int lcolb = (lane >> 4) * 16;

    float acc[MT][4][4];
#pragma unroll
    for (int i = 0; i < MT; i++)
#pragma unroll
        for (int j = 0; j < 4; j++)
#pragma unroll
            for (int c = 0; c < 4; c++) acc[i][j][c] = 0.f;

    auto fill = [&](int s, int k0) {
        const uint32_t base = sb + (uint32_t)(s * STAGEB);
#pragma unroll
        for (int idx = tid; idx < BM * 8; idx += 256) {
            int row = idx >> 3, g = idx & 7;
            int sz = (row < arows) ? 16 : 0;
            cp_async16(base + (uint32_t)(row * LDS + g * 16),
                       &A[(size_t)(bm + row) * K + k0 + g * 8], sz);
        }
#pragma unroll
        for (int idx = tid; idx < N * 8; idx += 256) {
            int row = idx >> 3, g = idx & 7;
            cp_async16(base + (uint32_t)(ABYTES + row * LDS + g * 16),
                       &W[(size_t)row * K + k0 + g * 8], 16);
        }
        CP_COMMIT();
    };

    fill(0, 0);
    if (NC > 1) fill(1, 64);

    for (int kc = 0; kc < NC; kc++) {
        if (kc + 1 < NC) cp_wait<1>(); else cp_wait<0>();
        __syncthreads();

        const uint32_t st = sb + (uint32_t)((kc % 3) * STAGEB);
        const uint32_t aB = st;
        const uint32_t wB = st + ABYTES;

#pragma unroll
        for (int ks = 0; ks < 4; ks++) {
            const uint32_t cb = (uint32_t)(ks * 32 + lcolb);
            uint32_t af[MT][4];
#pragma unroll
            for (int mt = 0; mt < MT; mt++)
                ldsm_x4(af[mt], aB + (uint32_t)((wm + mt * 16 + lrow) * LDS) + cb);
            uint32_t bf[2][4];
#pragma unroll
            for (int np = 0; np < 2; np++)
                ldsm_x4(bf[np], wB + (uint32_t)((wn + np * 16 + lrow) * LDS) + cb);
#pragma unroll
            for (int mt = 0; mt < MT; mt++)
#pragma unroll
                for (int nt = 0; nt < 4; nt++) {
                    int np = nt >> 1, h = nt & 1;
                    mma_f16(acc[mt][nt], af[mt], bf[np][h], bf[np][h + 2]);
                }
        }

        if (kc + 2 < NC) fill((kc + 2) % 3, (kc + 2) * 64);
    }

#pragma unroll
    for (int mt = 0; mt < MT; mt++) {
#pragma unroll
        for (int nt = 0; nt < 4; nt++) {
            int r0 = wm + mt * 16 + (lane >> 2);
            int c0 = wn + nt * 8 + (lane & 3) * 2;
            if (r0 < arows)
                *reinterpret_cast<__half2*>(&out[(size_t)(bm + r0) * N + c0]) =
                    __floats2half2_rn(acc[mt][nt][0], acc[mt][nt][1]);
            if (r0 + 8 < arows)
                *reinterpret_cast<__half2*>(&out[(size_t)(bm + r0 + 8) * N + c0]) =
                    __floats2half2_rn(acc[mt][nt][2], acc[mt][nt][3]);
        }
    }
}

// ---------------------------------------------------------------------------
// SpMM (H=128), fp16 gather / packed-f32x2 accumulate / ReLU / fp16 store.
// ---------------------------------------------------------------------------
__device__ __forceinline__ void fma_h4p(uint64_t& a01, uint64_t& a23,
                                        uint64_t vv, uint2 zz) {
    float2 f0 = __half22float2(*reinterpret_cast<__half2*>(&zz.x));
    float2 f1 = __half22float2(*reinterpret_cast<__half2*>(&zz.y));
    ffma2(a01, vv, pack_f32x2(f0.x, f0.y));
    ffma2(a23, vv, pack_f32x2(f1.x, f1.y));
}

__global__ void __launch_bounds__(256) spmm128_h_kernel(const int* __restrict__ edge_col,
                                                        const float* __restrict__ edge_val,
                                                        const __half* __restrict__ Z,
                                                        __half* __restrict__ out) {
    int gw   = (blockIdx.x * blockDim.x + threadIdx.x) >> 5;
    int lane = threadIdx.x & 31;
    if (gw >= N_NODES) return;
    int s = g_rowptr[gw];
    int e = g_rowptr[gw + 1];

    uint64_t a01 = pack_f32x2(0.f, 0.f);
    uint64_t a23 = pack_f32x2(0.f, 0.f);
    int i = s;
    for (; i + 8 <= e; i += 8) {
        int   c[8];
        float v[8];
        uint2 z[8];
#pragma unroll
        for (int u = 0; u < 8; u++) {
            c[u] = __ldg(&edge_col[i + u]);
            v[u] = __ldg(&edge_val[i + u]);
        }
#pragma unroll
        for (int u = 0; u < 8; u++)
            z[u] = *reinterpret_cast<const uint2*>(&Z[(size_t)c[u] * H_DIM + lane * 4]);
#pragma unroll
        for (int u = 0; u < 8; u++)
            fma_h4p(a01, a23, pack_f32x2(v[u], v[u]), z[u]);
    }
    for (; i < e; i++) {
        int   col = __ldg(&edge_col[i]);
        float val = __ldg(&edge_val[i]);
        uint2 zz = *reinterpret_cast<const uint2*>(&Z[(size_t)col * H_DIM + lane * 4]);
        fma_h4p(a01, a23, pack_f32x2(val, val), zz);
    }
    float4 acc;
    unpack_f32x2(a01, acc.x, acc.y);
    unpack_f32x2(a23, acc.z, acc.w);
    acc.x = fmaxf(acc.x, 0.f);
    acc.y = fmaxf(acc.y, 0.f);
    acc.z = fmaxf(acc.z, 0.f);
    acc.w = fmaxf(acc.w, 0.f);
    uint2 ov = make_uint2(pack_h2(make_float2(acc.x, acc.y)),
                          pack_h2(make_float2(acc.z, acc.w)));
    *reinterpret_cast<uint2*>(&out[(size_t)gw * H_DIM + lane * 4]) = ov;
}

// ---------------------------------------------------------------------------
// Final SpMM (F=64), fp16 gather, packed-f32x2 accumulate, fused row softmax.
// ---------------------------------------------------------------------------
__global__ void __launch_bounds__(256) spmm64_softmax_kernel(const int* __restrict__ edge_col,
                                                             const float* __restrict__ edge_val,
                                                             const __half* __restrict__ Z,
                                                             float* __restrict__ out) {
    int gw   = (blockIdx.x * blockDim.x + threadIdx.x) >> 5;
    int lane = threadIdx.x & 31;
    if (gw >= N_NODES) return;
    int s = g_rowptr[gw];
    int e = g_rowptr[gw + 1];

    uint64_t a01 = pack_f32x2(0.f, 0.f);
    int i = s;
    for (; i + 4 <= e; i += 4) {
#pragma unroll
        for (int u = 0; u < 4; u++) {
            int   col = __ldg(&edge_col[i + u]);
            float val = __ldg(&edge_val[i + u]);
            uint32_t zz = *reinterpret_cast<const uint32_t*>(&Z[(size_t)col * F_DIM + lane * 2]);
            float2 f = __half22float2(*reinterpret_cast<__half2*>(&zz));
            ffma2(a01, pack_f32x2(val, val), pack_f32x2(f.x, f.y));
        }
    }
    for (; i < e; i++) {
        int   col = __ldg(&edge_col[i]);
        float val = __ldg(&edge_val[i]);
        uint32_t zz = *reinterpret_cast<const uint32_t*>(&Z[(size_t)col * F_DIM + lane * 2]);
        float2 f = __half22float2(*reinterpret_cast<__half2*>(&zz));
        ffma2(a01, pack_f32x2(val, val), pack_f32x2(f.x, f.y));
    }
    float a0, a1;
    unpack_f32x2(a01, a0, a1);
    float m = fmaxf(a0, a1);
#pragma unroll
    for (int off = 16; off > 0; off >>= 1)
        m = fmaxf(m, __shfl_xor_sync(0xFFFFFFFFu, m, off));
    float e0 = expf(a0 - m);
    float e1 = expf(a1 - m);
    float ssum = e0 + e1;
#pragma unroll
    for (int off = 16; off > 0; off >>= 1)
        ssum += __shfl_xor_sync(0xFFFFFFFFu, ssum, off);
    float inv = 1.0f / ssum;
    *reinterpret_cast<float2*>(&out[(size_t)gw * F_DIM + lane * 2]) =
        make_float2(e0 * inv, e1 * inv);
}

// ---------------------------------------------------------------------------
// Launch
// ---------------------------------------------------------------------------
extern "C" void kernel_launch(void* const* d_in, const int* in_sizes, int n_in,
                              void* d_out, int out_size) {
    const float* X        = (const float*)d_in[0];
    const int*   edge_row = (const int*)d_in[1];
    const int*   edge_col = (const int*)d_in[2];
    const float* edge_val = (const float*)d_in[3];
    const float* W0       = (const float*)d_in[4];
    const float* Wh0      = (const float*)d_in[5];
    const float* W1       = (const float*)d_in[6];
    float*       out      = (float*)d_out;

    __half *h1, *h2, *Wh;
    cudaGetSymbolAddress((void**)&h1, g_hbuf1);
    cudaGetSymbolAddress((void**)&h2, g_hbuf2);
    cudaGetSymbolAddress((void**)&Wh, g_Wh);

    constexpr int SMEM_L0   = 4 * (64 * 160 + 128 * 80);   // 81920
    constexpr int SMEM_H128 = 3 * (128 + 128) * 144;       // 110592
    constexpr int SMEM_H64  = 3 * (128 + 64) * 144;        // 82944
    cudaFuncSetAttribute((const void*)gemm_l0,
                         cudaFuncAttributeMaxDynamicSharedMemorySize, SMEM_L0);
    cudaFuncSetAttribute((const void*)gemm_h<128, 128>,
                         cudaFuncAttributeMaxDynamicSharedMemorySize, SMEM_H128);
    cudaFuncSetAttribute((const void*)gemm_h<64, 128>,
                         cudaFuncAttributeMaxDynamicSharedMemorySize, SMEM_H64);

    const int l0_grid   = (N_NODES + 63) / 64;         // 1563
    const int gemm_grid = (N_NODES + 127) / 128;       // 782
    const int spmm_grid = (N_NODES * 32 + 255) / 256;  // 12500

    prep_kernel<<<(N_NODES + 1 + 255) / 256, 256>>>(edge_row, W0, Wh0, W1, Wh);

    // Layer 0: h1 = X @ W0h^T (fused fp32->fp16) ; h2 = relu(A @ h1)
    gemm_l0<<<l0_grid, 256, SMEM_L0>>>(X, Wh, h1, N_NODES);
    spmm128_h_kernel<<<spmm_grid, 256>>>(edge_col, edge_val, h1, h2);

    // Hidden: h1 = h2 @ Wh0h^T ; h2 = relu(A @ h1)
    gemm_h<128, 128><<<gemm_grid, 256, SMEM_H128>>>(h2, Wh + 32768, h1, N_NODES);
    spmm128_h_kernel<<<spmm_grid, 256>>>(edge_col, edge_val, h1, h2);

    // Output: h1 = h2 @ W1h^T ; out = softmax(A @ h1)
    gemm_h<64, 128><<<gemm_grid, 256, SMEM_H64>>>(h2, Wh + 49152, h1, N_NODES);
    spmm64_softmax_kernel<<<spmm_grid, 256>>>(edge_col, edge_val, h1, out);
}

// round 17
// speedup vs baseline: 1.1162x; 1.0129x over previous
#include <cuda_runtime.h>
#include <cuda_fp16.h>
#include <math.h>
#include <stdint.h>

#define N_NODES 100000
#define E_EDGES 1600000
#define C_DIM 256
#define H_DIM 128
#define F_DIM 64

// Scratch (__device__ globals; no allocation allowed)
__device__ __half g_hbuf1[N_NODES * H_DIM];   // GEMM outputs (pre-aggregation)
__device__ __half g_hbuf2[N_NODES * H_DIM];   // SpMM outputs (activations)
__device__ __half g_Wh[57344];                // fp16 W0 | Wh0 | W1
__device__ int    g_rowptr[N_NODES + 1];

// ---------------------------------------------------------------------------
// Helpers
// ---------------------------------------------------------------------------
__device__ __forceinline__ uint32_t smem_u32(const void* p) {
    uint32_t a;
    asm("{ .reg .u64 t; cvta.to.shared.u64 t, %1; cvt.u32.u64 %0, t; }" : "=r"(a) : "l"(p));
    return a;
}
__device__ __forceinline__ void ldsm_x4(uint32_t (&r)[4], uint32_t addr) {
    asm volatile("ldmatrix.sync.aligned.m8n8.x4.shared.b16 {%0,%1,%2,%3}, [%4];"
                 : "=r"(r[0]), "=r"(r[1]), "=r"(r[2]), "=r"(r[3]) : "r"(addr));
}
__device__ __forceinline__ void mma_f16(float (&d)[4], const uint32_t (&a)[4],
                                        uint32_t b0, uint32_t b1) {
    asm volatile(
        "mma.sync.aligned.m16n8k16.row.col.f32.f16.f16.f32 "
        "{%0,%1,%2,%3}, {%4,%5,%6,%7}, {%8,%9}, {%0,%1,%2,%3};"
        : "+f"(d[0]), "+f"(d[1]), "+f"(d[2]), "+f"(d[3])
        : "r"(a[0]), "r"(a[1]), "r"(a[2]), "r"(a[3]), "r"(b0), "r"(b1));
}
__device__ __forceinline__ void cp_async16(uint32_t dst, const void* src, int srcsize) {
    asm volatile("cp.async.cg.shared.global [%0], [%1], 16, %2;"
                 :: "r"(dst), "l"(src), "r"(srcsize));
}
#define CP_COMMIT() asm volatile("cp.async.commit_group;" ::: "memory")
template<int NW> __device__ __forceinline__ void cp_wait() {
    asm volatile("cp.async.wait_group %0;" :: "n"(NW) : "memory");
}
__device__ __forceinline__ uint32_t pack_h2(float2 v) {
    __half2 h = __floats2half2_rn(v.x, v.y);
    return *reinterpret_cast<uint32_t*>(&h);
}

// Packed f32x2 (Blackwell FFMA2) — bit-identical to scalar fmaf pairs.
__device__ __forceinline__ uint64_t pack_f32x2(float lo, float hi) {
    uint64_t r;
    asm("mov.b64 %0, {%1, %2};" : "=l"(r) : "f"(lo), "f"(hi));
    return r;
}
__device__ __forceinline__ void unpack_f32x2(uint64_t v, float& lo, float& hi) {
    asm("mov.b64 {%0, %1}, %2;" : "=f"(lo), "=f"(hi) : "l"(v));
}
__device__ __forceinline__ void ffma2(uint64_t& d, uint64_t a, uint64_t b) {
    asm("fma.rn.f32x2 %0, %1, %2, %0;" : "+l"(d) : "l"(a), "l"(b));
}

// ---------------------------------------------------------------------------
// Prep: rowptr + merged weight cast in ONE launch
// ---------------------------------------------------------------------------
__global__ void prep_kernel(const int* __restrict__ edge_row,
                            const float* __restrict__ W0,
                            const float* __restrict__ Wh0,
                            const float* __restrict__ W1,
                            __half* __restrict__ dst) {
    int i = blockIdx.x * blockDim.x + threadIdx.x;
    if (i <= N_NODES) {
        int lo = 0, hi = E_EDGES;
        while (lo < hi) {
            int mid = (lo + hi) >> 1;
            if (edge_row[mid] < i) lo = mid + 1;
            else hi = mid;
        }
        g_rowptr[i] = lo;
    }
    if (i < 14336) {                              // 57344 / 4 float4 groups
        const float* src;
        int j;
        if (i < 8192)       { src = W0;  j = i; }
        else if (i < 12288) { src = Wh0; j = i - 8192; }
        else                { src = W1;  j = i - 12288; }
        float4 v = reinterpret_cast<const float4*>(src)[j];
        uint2 o = make_uint2(pack_h2(make_float2(v.x, v.y)),
                             pack_h2(make_float2(v.z, v.w)));
        reinterpret_cast<uint2*>(dst)[i] = o;
    }
}

// ---------------------------------------------------------------------------
// Layer-0 GEMM: A fp32 (staged raw, cvt on fragment load), W fp16 (ldmatrix).
// BM=64 tile, 4 stages, wait<2>, 2 CTAs/SM.  (R16 config)
// ---------------------------------------------------------------------------
__global__ void __launch_bounds__(256, 2) gemm_l0(const float* __restrict__ A,
                                                  const __half* __restrict__ W,
                                                  __half* __restrict__ out, int M) {
    constexpr int BM = 64, N = 128, K = 256, BK = 32;
    constexpr int NC = K / BK;                  // 8
    constexpr int LDSA = 40;                    // floats per A row (160B)
    constexpr int ABYTES = BM * LDSA * 4;       // 10240
    constexpr int LDSW = 80;                    // bytes per W row
    constexpr int WBYTES = N * LDSW;            // 10240
    constexpr int STAGEB = ABYTES + WBYTES;     // 20480 (x4 = 81920)
    constexpr int MT = 2;

    extern __shared__ char smem[];
    const uint32_t sb = smem_u32(smem);

    const int tid  = threadIdx.x;
    const int wid  = tid >> 5;
    const int lane = tid & 31;
    const int wm   = (wid >> 2) * 32;
    const int wn   = (wid & 3) * 32;
    const int bm   = blockIdx.x * BM;
    const int arows = min(BM, M - bm);

    const int fr    = lane >> 2;
    const int fc    = lane & 3;
    const int lrow  = lane & 15;
    const int lcolb = (lane >> 4) * 16;

    float acc[MT][4][4];
#pragma unroll
    for (int i = 0; i < MT; i++)
#pragma unroll
        for (int j = 0; j < 4; j++)
#pragma unroll
            for (int c = 0; c < 4; c++) acc[i][j][c] = 0.f;

    auto fill = [&](int s, int k0) {
        const uint32_t base = sb + (uint32_t)(s * STAGEB);
#pragma unroll
        for (int idx = tid; idx < BM * 8; idx += 256) {
            int row = idx >> 3, g = idx & 7;
            int sz = (row < arows) ? 16 : 0;
            cp_async16(base + (uint32_t)(row * 160 + g * 16),
                       &A[(size_t)(bm + row) * K + k0 + g * 4], sz);
        }
#pragma unroll
        for (int idx = tid; idx < N * 4; idx += 256) {
            int row = idx >> 2, g = idx & 3;
            cp_async16(base + (uint32_t)(ABYTES + row * LDSW + g * 16),
                       &W[(size_t)row * K + k0 + g * 8], 16);
        }
        CP_COMMIT();
    };

    fill(0, 0);
    fill(1, BK);
    fill(2, 2 * BK);

    for (int kc = 0; kc < NC; kc++) {
        if (kc + 2 < NC)      cp_wait<2>();
        else if (kc + 1 < NC) cp_wait<1>();
        else                  cp_wait<0>();
        __syncthreads();

        const char*  stg = smem + (kc & 3) * STAGEB;
        const float* sA  = reinterpret_cast<const float*>(stg);
        const uint32_t wB = sb + (uint32_t)((kc & 3) * STAGEB + ABYTES);

#pragma unroll
        for (int ks = 0; ks < 2; ks++) {
            uint32_t af[MT][4];
#pragma unroll
            for (int mt = 0; mt < MT; mt++) {
                int base = (wm + mt * 16 + fr) * LDSA + ks * 16 + fc * 2;
                float2 v0 = *reinterpret_cast<const float2*>(&sA[base]);
                float2 v1 = *reinterpret_cast<const float2*>(&sA[base + 8 * LDSA]);
                float2 v2 = *reinterpret_cast<const float2*>(&sA[base + 8]);
                float2 v3 = *reinterpret_cast<const float2*>(&sA[base + 8 * LDSA + 8]);
                af[mt][0] = pack_h2(v0);
                af[mt][1] = pack_h2(v1);
                af[mt][2] = pack_h2(v2);
                af[mt][3] = pack_h2(v3);
            }
            uint32_t bf[2][4];
#pragma unroll
            for (int np = 0; np < 2; np++)
                ldsm_x4(bf[np], wB + (uint32_t)((wn + np * 16 + lrow) * LDSW
                                                + ks * 32 + lcolb));
#pragma unroll
            for (int mt = 0; mt < MT; mt++)
#pragma unroll
                for (int nt = 0; nt < 4; nt++) {
                    int np = nt >> 1, h = nt & 1;
                    mma_f16(acc[mt][nt], af[mt], bf[np][h], bf[np][h + 2]);
                }
        }

        if (kc + 3 < NC) fill((kc + 3) & 3, (kc + 3) * BK);
    }

#pragma unroll
    for (int mt = 0; mt < MT; mt++) {
#pragma unroll
        for (int nt = 0; nt < 4; nt++) {
            int r0 = wm + mt * 16 + fr;
            int c0 = wn + nt * 8 + fc * 2;
            if (r0 < arows)
                *reinterpret_cast<__half2*>(&out[(size_t)(bm + r0) * N + c0]) =
                    __floats2half2_rn(acc[mt][nt][0], acc[mt][nt][1]);
            if (r0 + 8 < arows)
                *reinterpret_cast<__half2*>(&out[(size_t)(bm + r0 + 8) * N + c0]) =
                    __floats2half2_rn(acc[mt][nt][2], acc[mt][nt][3]);
        }
    }
}

// ---------------------------------------------------------------------------
// fp16 HMMA GEMM (layers 1-2): BM=128, BK=64, 3-stage, 2 CTAs/SM. (R14/R16)
// ---------------------------------------------------------------------------
template<int N, int K>
__global__ void __launch_bounds__(256, 2) gemm_h(const __half* __restrict__ A,
                                                 const __half* __restrict__ W,
                                                 __half* __restrict__ out, int M) {
    constexpr int BM = 128;
    constexpr int LDS = 144;
    constexpr int ABYTES = BM * LDS;
    constexpr int WBYTES = N * LDS;
    constexpr int STAGEB = ABYTES + WBYTES;
    constexpr int NC = K / 64;
    constexpr int WCOLS = N / 32;
    constexpr int WTM = BM / (8 / WCOLS);
    constexpr int MT = WTM / 16;

    extern __shared__ char smem[];
    const uint32_t sb = smem_u32(smem);

    const int tid  = threadIdx.x;
    const int wid  = tid >> 5;
    const int lane = tid & 31;
    const int wm   = (wid / WCOLS) * WTM;
    const int wn   = (wid % WCOLS) * 32;
    const int bm   = blockIdx.x * BM;
    const int arows = min(BM, M - bm);

    const int lrow  = lane & 15;
    const int lcolb = (lane >> 4) * 16;

    float acc[MT][4][4];
#pragma unroll
    for (int i = 0; i < MT; i++)
#pragma unroll
        for (int j = 0; j < 4; j++)
#pragma unroll
            for (int c = 0; c < 4; c++) acc[i][j][c] = 0.f;

    auto fill = [&](int s, int k0) {
        const uint32_t base = sb + (uint32_t)(s * STAGEB);
#pragma unroll
        for (int idx = tid; idx < BM * 8; idx += 256) {
            int row = idx >> 3, g = idx & 7;
            int sz = (row < arows) ? 16 : 0;
            cp_async16(base + (uint32_t)(row * LDS + g * 16),
                       &A[(size_t)(bm + row) * K + k0 + g * 8], sz);
        }
#pragma unroll
        for (int idx = tid; idx < N * 8; idx += 256) {
            int row = idx >> 3, g = idx & 7;
            cp_async16(base + (uint32_t)(ABYTES + row * LDS + g * 16),
                       &W[(size_t)row * K + k0 + g * 8], 16);
        }
        CP_COMMIT();
    };

    fill(0, 0);
    if (NC > 1) fill(1, 64);

    for (int kc = 0; kc < NC; kc++) {
        if (kc + 1 < NC) cp_wait<1>(); else cp_wait<0>();
        __syncthreads();

        const uint32_t st = sb + (uint32_t)((kc % 3) * STAGEB);
        const uint32_t aB = st;
        const uint32_t wB = st + ABYTES;

#pragma unroll
        for (int ks = 0; ks < 4; ks++) {
            const uint32_t cb = (uint32_t)(ks * 32 + lcolb);
            uint32_t af[MT][4];
#pragma unroll
            for (int mt = 0; mt < MT; mt++)
                ldsm_x4(af[mt], aB + (uint32_t)((wm + mt * 16 + lrow) * LDS) + cb);
            uint32_t bf[2][4];
#pragma unroll
            for (int np = 0; np < 2; np++)
                ldsm_x4(bf[np], wB + (uint32_t)((wn + np * 16 + lrow) * LDS) + cb);
#pragma unroll
            for (int mt = 0; mt < MT; mt++)
#pragma unroll
                for (int nt = 0; nt < 4; nt++) {
                    int np = nt >> 1, h = nt & 1;
                    mma_f16(acc[mt][nt], af[mt], bf[np][h], bf[np][h + 2]);
                }
        }

        if (kc + 2 < NC) fill((kc + 2) % 3, (kc + 2) * 64);
    }

#pragma unroll
    for (int mt = 0; mt < MT; mt++) {
#pragma unroll
        for (int nt = 0; nt < 4; nt++) {
            int r0 = wm + mt * 16 + (lane >> 2);
            int c0 = wn + nt * 8 + (lane & 3) * 2;
            if (r0 < arows)
                *reinterpret_cast<__half2*>(&out[(size_t)(bm + r0) * N + c0]) =
                    __floats2half2_rn(acc[mt][nt][0], acc[mt][nt][1]);
            if (r0 + 8 < arows)
                *reinterpret_cast<__half2*>(&out[(size_t)(bm + r0 + 8) * N + c0]) =
                    __floats2half2_rn(acc[mt][nt][2], acc[mt][nt][3]);
        }
    }
}

// ---------------------------------------------------------------------------
// SpMM (H=128), PAIRED-EDGE gather: warp = two 16-lane halves, each half
// loads a different edge's full 128-col row as uint4 (LDG.128). One gather
// instruction serves 2 edges. Per-half accumulators merged by shfl_xor(16).
// fp32 accumulate, ReLU, fp16 store.
// ---------------------------------------------------------------------------
__device__ __forceinline__ void fma_h8p(uint64_t (&acc)[4], uint64_t vv, uint4 z) {
    float2 f0 = __half22float2(*reinterpret_cast<__half2*>(&z.x));
    float2 f1 = __half22float2(*reinterpret_cast<__half2*>(&z.y));
    float2 f2 = __half22float2(*reinterpret_cast<__half2*>(&z.z));
    float2 f3 = __half22float2(*reinterpret_cast<__half2*>(&z.w));
    ffma2(acc[0], vv, pack_f32x2(f0.x, f0.y));
    ffma2(acc[1], vv, pack_f32x2(f1.x, f1.y));
    ffma2(acc[2], vv, pack_f32x2(f2.x, f2.y));
    ffma2(acc[3], vv, pack_f32x2(f3.x, f3.y));
}

__global__ void __launch_bounds__(256) spmm128_h_kernel(const int* __restrict__ edge_col,
                                                        const float* __restrict__ edge_val,
                                                        const __half* __restrict__ Z,
                                                        __half* __restrict__ out) {
    int gw   = (blockIdx.x * blockDim.x + threadIdx.x) >> 5;
    int lane = threadIdx.x & 31;
    if (gw >= N_NODES) return;
    int s = g_rowptr[gw];
    int e = g_rowptr[gw + 1];

    const int h = lane >> 4;      // half id (which edge of the pair)
    const int l = lane & 15;      // 16-byte chunk within the row

    uint64_t acc[4];
    acc[0] = acc[1] = acc[2] = acc[3] = pack_f32x2(0.f, 0.f);

    int i = s;
    // 4 pairs (8 edges) per iteration
    for (; i + 8 <= e; i += 8) {
        int   c[4];
        float v[4];
        uint4 z[4];
#pragma unroll
        for (int u = 0; u < 4; u++) {
            int idx = i + 2 * u + h;
            c[u] = __ldg(&edge_col[idx]);
            v[u] = __ldg(&edge_val[idx]);
        }
#pragma unroll
        for (int u = 0; u < 4; u++)
            z[u] = *reinterpret_cast<const uint4*>(&Z[(size_t)c[u] * H_DIM + l * 8]);
#pragma unroll
        for (int u = 0; u < 4; u++)
            fma_h8p(acc, pack_f32x2(v[u], v[u]), z[u]);
    }
    // single pairs
    for (; i + 2 <= e; i += 2) {
        int   col = __ldg(&edge_col[i + h]);
        float val = __ldg(&edge_val[i + h]);
        uint4 z = *reinterpret_cast<const uint4*>(&Z[(size_t)col * H_DIM + l * 8]);
        fma_h8p(acc, pack_f32x2(val, val), z);
    }
    // odd tail: half 0 handles the edge, half 1 contributes zero
    if (i < e) {
        int   col = __ldg(&edge_col[i]);
        float val = (h == 0) ? __ldg(&edge_val[i]) : 0.f;
        uint4 z = *reinterpret_cast<const uint4*>(&Z[(size_t)col * H_DIM + l * 8]);
        fma_h8p(acc, pack_f32x2(val, val), z);
    }

    // merge halves, ReLU, store (lanes 0-15 cover the full row: 16 x 16B)
    float f[8];
#pragma unroll
    for (int j = 0; j < 4; j++) {
        float lo, hi;
        unpack_f32x2(acc[j], lo, hi);
        lo += __shfl_xor_sync(0xFFFFFFFFu, lo, 16);
        hi += __shfl_xor_sync(0xFFFFFFFFu, hi, 16);
        f[2 * j]     = fmaxf(lo, 0.f);
        f[2 * j + 1] = fmaxf(hi, 0.f);
    }
    if (h == 0) {
        uint4 ov;
        ov.x = pack_h2(make_float2(f[0], f[1]));
        ov.y = pack_h2(make_float2(f[2], f[3]));
        ov.z = pack_h2(make_float2(f[4], f[5]));
        ov.w = pack_h2(make_float2(f[6], f[7]));
        *reinterpret_cast<uint4*>(&out[(size_t)gw * H_DIM + l * 8]) = ov;
    }
}

// ---------------------------------------------------------------------------
// Final SpMM (F=64), fp16 gather, packed-f32x2 accumulate, fused row softmax.
// (R14/R16 form — unchanged)
// ---------------------------------------------------------------------------
__global__ void __launch_bounds__(256) spmm64_softmax_kernel(const int* __restrict__ edge_col,
                                                             const float* __restrict__ edge_val,
                                                             const __half* __restrict__ Z,
                                                             float* __restrict__ out) {
    int gw   = (blockIdx.x * blockDim.x + threadIdx.x) >> 5;
    int lane = threadIdx.x & 31;
    if (gw >= N_NODES) return;
    int s = g_rowptr[gw];
    int e = g_rowptr[gw + 1];

    uint64_t a01 = pack_f32x2(0.f, 0.f);
    int i = s;
    for (; i + 4 <= e; i += 4) {
#pragma unroll
        for (int u = 0; u < 4; u++) {
            int   col = __ldg(&edge_col[i + u]);
            float val = __ldg(&edge_val[i + u]);
            uint32_t zz = *reinterpret_cast<const uint32_t*>(&Z[(size_t)col * F_DIM + lane * 2]);
            float2 f = __half22float2(*reinterpret_cast<__half2*>(&zz));
            ffma2(a01, pack_f32x2(val, val), pack_f32x2(f.x, f.y));
        }
    }
    for (; i < e; i++) {
        int   col = __ldg(&edge_col[i]);
        float val = __ldg(&edge_val[i]);
        uint32_t zz = *reinterpret_cast<const uint32_t*>(&Z[(size_t)col * F_DIM + lane * 2]);
        float2 f = __half22float2(*reinterpret_cast<__half2*>(&zz));
        ffma2(a01, pack_f32x2(val, val), pack_f32x2(f.x, f.y));
    }
    float a0, a1;
    unpack_f32x2(a01, a0, a1);
    float m = fmaxf(a0, a1);
#pragma unroll
    for (int off = 16; off > 0; off >>= 1)
        m = fmaxf(m, __shfl_xor_sync(0xFFFFFFFFu, m, off));
    float e0 = expf(a0 - m);
    float e1 = expf(a1 - m);
    float ssum = e0 + e1;
#pragma unroll
    for (int off = 16; off > 0; off >>= 1)
        ssum += __shfl_xor_sync(0xFFFFFFFFu, ssum, off);
    float inv = 1.0f / ssum;
    *reinterpret_cast<float2*>(&out[(size_t)gw * F_DIM + lane * 2]) =
        make_float2(e0 * inv, e1 * inv);
}

// ---------------------------------------------------------------------------
// Launch
// ---------------------------------------------------------------------------
extern "C" void kernel_launch(void* const* d_in, const int* in_sizes, int n_in,
                              void* d_out, int out_size) {
    const float* X        = (const float*)d_in[0];
    const int*   edge_row = (const int*)d_in[1];
    const int*   edge_col = (const int*)d_in[2];
    const float* edge_val = (const float*)d_in[3];
    const float* W0       = (const float*)d_in[4];
    const float* Wh0      = (const float*)d_in[5];
    const float* W1       = (const float*)d_in[6];
    float*       out      = (float*)d_out;

    __half *h1, *h2, *Wh;
    cudaGetSymbolAddress((void**)&h1, g_hbuf1);
    cudaGetSymbolAddress((void**)&h2, g_hbuf2);
    cudaGetSymbolAddress((void**)&Wh, g_Wh);

    constexpr int SMEM_L0   = 4 * (64 * 160 + 128 * 80);   // 81920
    constexpr int SMEM_H128 = 3 * (128 + 128) * 144;       // 110592
    constexpr int SMEM_H64  = 3 * (128 + 64) * 144;        // 82944
    cudaFuncSetAttribute((const void*)gemm_l0,
                         cudaFuncAttributeMaxDynamicSharedMemorySize, SMEM_L0);
    cudaFuncSetAttribute((const void*)gemm_h<128, 128>,
                         cudaFuncAttributeMaxDynamicSharedMemorySize, SMEM_H128);
    cudaFuncSetAttribute((const void*)gemm_h<64, 128>,
                         cudaFuncAttributeMaxDynamicSharedMemorySize, SMEM_H64);

    const int l0_grid   = (N_NODES + 63) / 64;         // 1563
    const int gemm_grid = (N_NODES + 127) / 128;       // 782
    const int spmm_grid = (N_NODES * 32 + 255) / 256;  // 12500

    prep_kernel<<<(N_NODES + 1 + 255) / 256, 256>>>(edge_row, W0, Wh0, W1, Wh);

    // Layer 0: h1 = X @ W0h^T (fused fp32->fp16) ; h2 = relu(A @ h1)
    gemm_l0<<<l0_grid, 256, SMEM_L0>>>(X, Wh, h1, N_NODES);
    spmm128_h_kernel<<<spmm_grid, 256>>>(edge_col, edge_val, h1, h2);

    // Hidden: h1 = h2 @ Wh0h^T ; h2 = relu(A @ h1)
    gemm_h<128, 128><<<gemm_grid, 256, SMEM_H128>>>(h2, Wh + 32768, h1, N_NODES);
    spmm128_h_kernel<<<spmm_grid, 256>>>(edge_col, edge_val, h1, h2);

    // Output: h1 = h2 @ W1h^T ; out = softmax(A @ h1)
    gemm_h<64, 128><<<gemm_grid, 256, SMEM_H64>>>(h2, Wh + 49152, h1, N_NODES);
    spmm64_softmax_kernel<<<spmm_grid, 256>>>(edge_col, edge_val, h1, out);
}